// round 2
// baseline (speedup 1.0000x reference)
#include <cuda_runtime.h>
#include <cstdint>

#define BB 64
#define SS 512
#define HH 1024
#define TT 17
#define NEG_INF (-3.402823466e+38f)

#define FMA2(acc, a, w) \
    asm("fma.rn.f32x2 %0, %1, %2, %0;" : "+l"(acc) : "l"(a), "l"(w))

// ---------------------------------------------------------------------------
// Kernel 1: feats = x @ W^T + b.  128 blocks x 256 threads, 1 row/thread.
// W (17x1024 f32 = 68KB) lives in dynamic smem; x streamed via __ldcs.
// ---------------------------------------------------------------------------
extern __shared__ float wsm[];   // 17*1024 floats

__global__ __launch_bounds__(256, 1)
void crf_gemm_kernel(const float* __restrict__ x,
                     const float* __restrict__ W,
                     const float* __restrict__ bvec,
                     float* __restrict__ feats)
{
    const int tid = threadIdx.x;

    // load all of W into smem (17408 floats = 4352 float4)
    {
        const float4* src = (const float4*)W;
        float4* dst = (float4*)wsm;
        for (int i = tid; i < (TT * HH) / 4; i += 256) dst[i] = src[i];
    }
    __syncthreads();

    const int row = blockIdx.x * 256 + tid;
    const float* xr = x + (size_t)row * HH;

    unsigned long long acc[TT];
#pragma unroll
    for (int t = 0; t < TT; t++) acc[t] = 0ull;

    for (int k = 0; k < HH; k += 4) {
        float4 av = __ldcs((const float4*)(xr + k));
        unsigned long long a01, a23;
        asm("mov.b64 %0, {%1, %2};" : "=l"(a01) : "f"(av.x), "f"(av.y));
        asm("mov.b64 %0, {%1, %2};" : "=l"(a23) : "f"(av.z), "f"(av.w));
#pragma unroll
        for (int t = 0; t < TT; t++) {
            ulonglong2 w = *(const ulonglong2*)(wsm + t * HH + k);
            FMA2(acc[t], a01, w.x);
            FMA2(acc[t], a23, w.y);
        }
    }

    float* o = feats + (size_t)row * TT;
#pragma unroll
    for (int t = 0; t < TT; t++) {
        float lo, hi;
        asm("mov.b64 {%0, %1}, %2;" : "=f"(lo), "=f"(hi) : "l"(acc[t]));
        o[t] = lo + hi + __ldg(&bvec[t]);
    }
}

// ---------------------------------------------------------------------------
// Kernel 2: masked Viterbi decode. One warp per batch element, lane = tag.
// ---------------------------------------------------------------------------

// max + first-occurrence argmax over v[0..16]; leaves max in v[0]
__device__ __forceinline__ int tree_argmax17(float v[TT])
{
    int ix[TT];
#pragma unroll
    for (int i = 0; i < TT; i++) ix[i] = i;
#define RED17(a, b) { bool g = v[b] > v[a]; float nv = fmaxf(v[a], v[b]); \
                      ix[a] = g ? ix[b] : ix[a]; v[a] = nv; }
    RED17(0, 1)  RED17(2, 3)   RED17(4, 5)   RED17(6, 7)
    RED17(8, 9)  RED17(10, 11) RED17(12, 13) RED17(14, 15)
    RED17(0, 2)  RED17(4, 6)   RED17(8, 10)  RED17(12, 14)
    RED17(0, 4)  RED17(8, 12)
    RED17(0, 8)
    RED17(0, 16)
#undef RED17
    return ix[0];
}

__global__ __launch_bounds__(32, 1)
void crf_viterbi_kernel(const float* __restrict__ feats,
                        const float* __restrict__ trans,
                        const float* __restrict__ start_trans,
                        const float* __restrict__ end_trans,
                        const int*   __restrict__ nwords,
                        float* __restrict__ out_tags)
{
    __shared__ float         feats_sh[SS * TT];      // 34816 B
    __shared__ unsigned char bp_sh[SS * TT];         //  8704 B
    __shared__ unsigned char Csh[15 * 32];           //   480 B

    const int b    = blockIdx.x;
    const int lane = threadIdx.x;
    const int n    = nwords[b];
    const unsigned FULL = 0xffffffffu;

    // preload this batch's feats
    {
        const float4* src = (const float4*)(feats + (size_t)b * SS * TT);
        float4* dst = (float4*)feats_sh;
        for (int i = lane; i < (SS * TT) / 4; i += 32) dst[i] = src[i];
    }
    // prefill identity backpointers for masked steps
    for (int t = n; t < SS; t++)
        if (lane < TT) bp_sh[t * TT + lane] = (unsigned char)lane;

    // transitions column for this lane: tc[i] = trans[i][lane]
    float tc[TT];
#pragma unroll
    for (int i = 0; i < TT; i++)
        tc[i] = (lane < TT) ? trans[i * TT + lane] : NEG_INF;

    __syncwarp();

    const int lanec = (lane < TT) ? lane : 0;
    float s = (lane < TT) ? (start_trans[lane] + feats_sh[lane]) : NEG_INF;
    int   M = lane;   // composed survivor map within current 32-step chunk

    for (int t = 1; t < SS; t++) {
        if (t < n) {
            float sv[TT];
#pragma unroll
            for (int i = 0; i < TT; i++) sv[i] = __shfl_sync(FULL, s, i);
            float v[TT];
#pragma unroll
            for (int i = 0; i < TT; i++) v[i] = sv[i] + tc[i];
            int bp = tree_argmax17(v);
            s = v[0] + feats_sh[t * TT + lanec];
            if (lane < TT) bp_sh[t * TT + lane] = (unsigned char)bp;
            M = __shfl_sync(FULL, M, bp);       // M_new[j] = M_old[bp_j]
        }
        if ((t & 31) == 0) {                    // t = 32,64,...,480
            int c = (t >> 5) - 1;               // chunk 0..14
            if (lane < TT) Csh[c * 32 + lane] = (unsigned char)M;
            M = lane;
            __syncwarp();
        }
    }
    // M now maps tag_511 -> tag_480

    // final argmax over s + end_trans (butterfly, first-index tie-break)
    {
        float v = (lane < TT) ? (s + end_trans[lane]) : NEG_INF;
        int ix = (lane < TT) ? lane : 99;
#pragma unroll
        for (int off = 16; off; off >>= 1) {
            float ov = __shfl_xor_sync(FULL, v, off);
            int   oi = __shfl_xor_sync(FULL, ix, off);
            if (ov > v || (ov == v && oi < ix)) { v = ov; ix = oi; }
        }
        M = __shfl_sync(FULL, M, ix);           // broadcast-safe gather
        // chain boundary tags: cur = tag at time 32c
        int last_tag = ix;
        int startTag = last_tag;                // lane 15 start (tag_511)
        int cur = M;                            // tag_480
        if (lane == 14) startTag = cur;
        __syncwarp();
        for (int c = 14; c >= 1; c--) {
            cur = (int)Csh[c * 32 + cur];       // tag_{32c}
            if (lane == c - 1) startTag = cur;
        }

        // parallel per-chunk backtrack: lane c handles t in (32c, min(32c+32,511)]
        float* outT = out_tags + (size_t)b * SS;
        if (lane < 16) {
            int tag = startTag;
            int tEnd = 32 * lane;
            int tStart = (lane == 15) ? (SS - 1) : (32 * (lane + 1));
            for (int t = tStart; t > tEnd; t--) {
                outT[t] = (t < n) ? (float)tag : 0.0f;
                tag = (int)bp_sh[t * TT + tag];
            }
            if (lane == 0) outT[0] = (float)tag;   // n >= 1, never masked
        }
    }
}

// ---------------------------------------------------------------------------
extern "C" void kernel_launch(void* const* d_in, const int* in_sizes, int n_in,
                              void* d_out, int out_size)
{
    const float* x     = (const float*)d_in[0];
    const float* W     = (const float*)d_in[1];
    const float* bvec  = (const float*)d_in[2];
    const float* trans = (const float*)d_in[3];
    const float* st    = (const float*)d_in[4];
    const float* en    = (const float*)d_in[5];
    const int*   nw    = (const int*)d_in[6];

    float* out   = (float*)d_out;
    float* tags  = out;                         // (B,S)  = 32768 floats
    float* feats = out + BB * SS;               // (B,S,T) = 557056 floats

    cudaFuncSetAttribute(crf_gemm_kernel,
                         cudaFuncAttributeMaxDynamicSharedMemorySize,
                         TT * HH * (int)sizeof(float));

    crf_gemm_kernel<<<128, 256, TT * HH * sizeof(float)>>>(x, W, bvec, feats);
    crf_viterbi_kernel<<<BB, 32>>>(feats, trans, st, en, nw, tags);
}